// round 5
// baseline (speedup 1.0000x reference)
#include <cuda_runtime.h>
#include <cuda_bf16.h>
#include <cstdint>

// ---------------------------------------------------------------------------
// CrossNetLayer on GB300 (sm_103a; PTX target compute_103 -> no tcgen05)
//   h = x @ W_enc + b_enc  -> mma.sync bf16 hi/lo-split GEMM (3-term, fp32 acc)
//   cross layers via closed form: out = a4(row) * h + u4, where
//     d_l = h.w_l (4 parallel dots), e_l = u_l.w_l, u_l = prefix sums of b,
//     s_l = a_l*d_l + e_l, a_{l+1} = a_l + s_l, a_0 = 1.
// ---------------------------------------------------------------------------

#define BDIM 1024
#define HDIM 1024
#define KDIM 1024
#define DEPTH 4

// Scratch (no cudaMalloc allowed)
__device__ float          g_h[BDIM * HDIM];
__device__ __nv_bfloat16  g_xhi[BDIM * KDIM];
__device__ __nv_bfloat16  g_xlo[BDIM * KDIM];
__device__ __nv_bfloat16  g_wthi[HDIM * KDIM];   // W transposed: [n][k]
__device__ __nv_bfloat16  g_wtlo[HDIM * KDIM];
__device__ float          g_e[DEPTH];            // e_l = u_l . w_l
__device__ float          g_u4[HDIM];            // u_4 = b0+b1+b2+b3

// ---------------------------------------------------------------------------
// helpers
// ---------------------------------------------------------------------------
__device__ __forceinline__ uint32_t smem_u32(const void* p) {
    uint32_t a;
    asm("{ .reg .u64 t; cvta.to.shared.u64 t, %1; cvt.u32.u64 %0, t; }"
        : "=r"(a) : "l"(p));
    return a;
}

__device__ __forceinline__ uint32_t swz(uint32_t off) {
    return off ^ ((off >> 3) & 0x70);   // SW128: 16B granule ^= row&7
}

__device__ __forceinline__ void cp_async16(uint32_t smem_addr, const void* gptr) {
    asm volatile("cp.async.cg.shared.global [%0], [%1], 16;"
                 :: "r"(smem_addr), "l"(gptr));
}

__device__ __forceinline__ void ldsm_x4(uint32_t* r, uint32_t addr) {
    asm volatile("ldmatrix.sync.aligned.m8n8.x4.shared.b16 {%0,%1,%2,%3}, [%4];"
                 : "=r"(r[0]), "=r"(r[1]), "=r"(r[2]), "=r"(r[3]) : "r"(addr));
}

__device__ __forceinline__ void mma_bf16(float* d, const uint32_t* a, const uint32_t* b) {
    asm volatile(
        "mma.sync.aligned.m16n8k16.row.col.f32.bf16.bf16.f32 "
        "{%0,%1,%2,%3}, {%4,%5,%6,%7}, {%8,%9}, {%0,%1,%2,%3};"
        : "+f"(d[0]), "+f"(d[1]), "+f"(d[2]), "+f"(d[3])
        : "r"(a[0]), "r"(a[1]), "r"(a[2]), "r"(a[3]), "r"(b[0]), "r"(b[1]));
}

// ---------------------------------------------------------------------------
// Kernel: convert x (fp32 row-major [B,K]) -> hi/lo bf16
// ---------------------------------------------------------------------------
__global__ __launch_bounds__(256, 1) void convert_x_kernel(const float* __restrict__ x)
{
    int i = (blockIdx.x * 256 + threadIdx.x) * 4;
    float4 v = *(const float4*)(x + i);
    __nv_bfloat16 h0 = __float2bfloat16(v.x);
    __nv_bfloat16 h1 = __float2bfloat16(v.y);
    __nv_bfloat16 h2 = __float2bfloat16(v.z);
    __nv_bfloat16 h3 = __float2bfloat16(v.w);
    __nv_bfloat16 l0 = __float2bfloat16(v.x - __bfloat162float(h0));
    __nv_bfloat16 l1 = __float2bfloat16(v.y - __bfloat162float(h1));
    __nv_bfloat16 l2 = __float2bfloat16(v.z - __bfloat162float(h2));
    __nv_bfloat16 l3 = __float2bfloat16(v.w - __bfloat162float(h3));
    __nv_bfloat162* ph = (__nv_bfloat162*)(g_xhi + i);
    __nv_bfloat162* pl = (__nv_bfloat162*)(g_xlo + i);
    ph[0] = __nv_bfloat162(h0, h1);
    ph[1] = __nv_bfloat162(h2, h3);
    pl[0] = __nv_bfloat162(l0, l1);
    pl[1] = __nv_bfloat162(l2, l3);
}

// ---------------------------------------------------------------------------
// Kernel: convert + transpose W_enc -> g_wt{hi,lo}; block (0,0) additionally
// computes e_l = (sum_{j<l} b_j) . w_l and u4 = sum_l b_l.
// ---------------------------------------------------------------------------
__global__ __launch_bounds__(256, 1) void convert_wt_kernel(
    const float* __restrict__ W,
    const float* __restrict__ ws, const float* __restrict__ bs)
{
    __shared__ float tile[32][33];
    const int bx = blockIdx.x;   // n tile
    const int by = blockIdx.y;   // k tile
    const int tx = threadIdx.x;  // 0..31
    const int ty = threadIdx.y;  // 0..7

#pragma unroll
    for (int j = 0; j < 4; j++) {
        int k = by * 32 + ty + 8 * j;
        tile[ty + 8 * j][tx] = W[(size_t)k * HDIM + bx * 32 + tx];
    }
    __syncthreads();
#pragma unroll
    for (int j = 0; j < 4; j++) {
        float v = tile[tx][ty + 8 * j];
        int n = bx * 32 + ty + 8 * j;
        int k = by * 32 + tx;
        __nv_bfloat16 h = __float2bfloat16(v);
        g_wthi[(size_t)n * KDIM + k] = h;
        g_wtlo[(size_t)n * KDIM + k] = __float2bfloat16(v - __bfloat162float(h));
    }

    // ---- block (0,0): e_l and u4 precompute ----
    if (bx == 0 && by == 0) {
        __shared__ float esum[3][8];
        const int tid = ty * 32 + tx;      // 0..255
        const int lane = tid & 31;
        const int wrp = tid >> 5;
        float p1 = 0.f, p2 = 0.f, p3 = 0.f;
#pragma unroll
        for (int j = 0; j < 4; j++) {
            int c = tid * 4 + j;
            float b0 = bs[0 * HDIM + c];
            float b1 = bs[1 * HDIM + c];
            float b2 = bs[2 * HDIM + c];
            float b3 = bs[3 * HDIM + c];
            p1 += b0 * ws[1 * HDIM + c];
            p2 += (b0 + b1) * ws[2 * HDIM + c];
            p3 += (b0 + b1 + b2) * ws[3 * HDIM + c];
            g_u4[c] = b0 + b1 + b2 + b3;
        }
#pragma unroll
        for (int o = 16; o > 0; o >>= 1) {
            p1 += __shfl_xor_sync(0xffffffffu, p1, o);
            p2 += __shfl_xor_sync(0xffffffffu, p2, o);
            p3 += __shfl_xor_sync(0xffffffffu, p3, o);
        }
        if (lane == 0) { esum[0][wrp] = p1; esum[1][wrp] = p2; esum[2][wrp] = p3; }
        __syncthreads();
        if (tid == 0) {
            float e1 = 0.f, e2 = 0.f, e3 = 0.f;
#pragma unroll
            for (int i = 0; i < 8; i++) { e1 += esum[0][i]; e2 += esum[1][i]; e3 += esum[2][i]; }
            g_e[0] = 0.0f; g_e[1] = e1; g_e[2] = e2; g_e[3] = e3;
        }
    }
}

// ---------------------------------------------------------------------------
// mma.sync GEMM: h = x @ W_enc + bias (bf16-split: hi*hi + hi*lo + lo*hi)
// CTA tile: BM=128, BN=64, BK=128 (two 64-col sub-tiles). Grid (16,8) = 128.
// 8 warps in 4(M) x 2(N); warp tile 32x32. SW128 swizzle, 2-stage cp.async.
// ---------------------------------------------------------------------------
#define GBM 128
#define GBN 64
#define GKC 128
#define NCHUNK (KDIM / GKC)     // 8

// stage layout (bytes): AH[2][16384], AL[2][16384], BH[2][8192], BL[2][8192]
#define SUB_AH 0
#define SUB_AL 32768
#define SUB_BH 65536
#define SUB_BL 81920
#define STAGE_BYTES 98304
#define GEMM_SMEM (2 * STAGE_BYTES)   // 196608

__global__ __launch_bounds__(256, 1) void gemm_mma_kernel(const float* __restrict__ bias)
{
    extern __shared__ char smem[];
    const int tid  = threadIdx.x;
    const int wid  = tid >> 5;
    const int lane = tid & 31;
    const int bn   = blockIdx.x;   // 0..15
    const int bm   = blockIdx.y;   // 0..7
    const uint32_t sb = smem_u32(smem);

    const int warp_m = wid >> 1;   // 0..3
    const int warp_n = wid & 1;    // 0..1

    // ---- precomputed load addressing (advance +256B per chunk) ----
    // A: 128 rows x 16 granules (256B/row) -> 2048 granules hi, 8 per thread
    const char* pAh[8]; const char* pAl[8]; uint32_t offA[8];
#pragma unroll
    for (int it = 0; it < 8; ++it) {
        int idx = tid + it * 256;
        int row = idx >> 4;          // 0..127
        int g   = idx & 15;          // 16B granule within 256B row
        size_t gb = ((size_t)(bm * GBM + row) * KDIM) * 2 + g * 16;
        pAh[it] = (const char*)g_xhi + gb;
        pAl[it] = (const char*)g_xlo + gb;
        offA[it] = (uint32_t)(g >> 3) * 16384 + swz(row * 128 + (g & 7) * 16);
    }
    // B: 64 rows x 16 granules -> 1024 granules hi, 4 per thread
    const char* pBh[4]; const char* pBl[4]; uint32_t offB[4];
#pragma unroll
    for (int it = 0; it < 4; ++it) {
        int idx = tid + it * 256;
        int row = idx >> 4;          // 0..63
        int g   = idx & 15;
        size_t gb = ((size_t)(bn * GBN + row) * KDIM) * 2 + g * 16;
        pBh[it] = (const char*)g_wthi + gb;
        pBl[it] = (const char*)g_wtlo + gb;
        offB[it] = (uint32_t)(g >> 3) * 8192 + swz(row * 128 + (g & 7) * 16);
    }

    // ---- ldmatrix per-lane offset components ----
    const int a_row_l = lane & 15;
    const int a_kb_l  = (lane >> 4) << 4;
    const int b_row_l = (lane & 7) + ((lane >> 4) << 3);
    const int b_kb_l  = ((lane >> 3) & 1) << 4;

    float acc[2][4][4];
#pragma unroll
    for (int mi = 0; mi < 2; mi++)
#pragma unroll
        for (int ni = 0; ni < 4; ni++)
#pragma unroll
            for (int j = 0; j < 4; j++) acc[mi][ni][j] = 0.0f;

    // ---- prologue: preload chunk 0 into stage 0 ----
#pragma unroll
    for (int it = 0; it < 8; ++it) {
        cp_async16(sb + SUB_AH + offA[it], pAh[it]);
        cp_async16(sb + SUB_AL + offA[it], pAl[it]);
    }
#pragma unroll
    for (int it = 0; it < 4; ++it) {
        cp_async16(sb + SUB_BH + offB[it], pBh[it]);
        cp_async16(sb + SUB_BL + offB[it], pBl[it]);
    }
    asm volatile("cp.async.commit_group;" ::: "memory");

    for (int c = 0; c < NCHUNK; ++c) {
        asm volatile("cp.async.wait_group 0;" ::: "memory");
        __syncthreads();   // chunk c visible; all warps done with stage (c+1)&1

        // issue loads for chunk c+1 into the other stage
        if (c + 1 < NCHUNK) {
            uint32_t dst = sb + ((c + 1) & 1) * STAGE_BYTES;
            size_t go = (size_t)(c + 1) * 256;
#pragma unroll
            for (int it = 0; it < 8; ++it) {
                cp_async16(dst + SUB_AH + offA[it], pAh[it] + go);
                cp_async16(dst + SUB_AL + offA[it], pAl[it] + go);
            }
#pragma unroll
            for (int it = 0; it < 4; ++it) {
                cp_async16(dst + SUB_BH + offB[it], pBh[it] + go);
                cp_async16(dst + SUB_BL + offB[it], pBl[it] + go);
            }
            asm volatile("cp.async.commit_group;" ::: "memory");
        }

        // compute on chunk c: 2 sub-tiles x 4 k-steps
        const uint32_t base = sb + (c & 1) * STAGE_BYTES;
#pragma unroll
        for (int sub = 0; sub < 2; sub++) {
            const uint32_t baseA = base + sub * 16384;
            const uint32_t baseB = base + sub * 8192;
#pragma unroll
            for (int kk = 0; kk < 4; kk++) {
                uint32_t RAh[2][4], RAl[2][4], RBh[8], RBl[8];
#pragma unroll
                for (int mi = 0; mi < 2; mi++) {
                    int row = warp_m * 32 + mi * 16 + a_row_l;
                    uint32_t off = swz(row * 128 + kk * 32 + a_kb_l);
                    ldsm_x4(RAh[mi], baseA + SUB_AH + off);
                    ldsm_x4(RAl[mi], baseA + SUB_AL + off);
                }
#pragma unroll
                for (int p = 0; p < 2; p++) {
                    int row = warp_n * 32 + p * 16 + b_row_l;
                    uint32_t off = swz(row * 128 + kk * 32 + b_kb_l);
                    ldsm_x4(&RBh[4 * p], baseB + SUB_BH + off);
                    ldsm_x4(&RBl[4 * p], baseB + SUB_BL + off);
                }
#pragma unroll
                for (int mi = 0; mi < 2; mi++)
#pragma unroll
                    for (int ni = 0; ni < 4; ni++) {
                        mma_bf16(acc[mi][ni], RAh[mi], &RBh[2 * ni]);   // hi*hi
                        mma_bf16(acc[mi][ni], RAh[mi], &RBl[2 * ni]);   // hi*lo
                        mma_bf16(acc[mi][ni], RAl[mi], &RBh[2 * ni]);   // lo*hi
                    }
            }
        }
        __syncthreads();   // all warps done reading stage (c&1) before next overwrite
    }

    // epilogue: acc -> g_h (+bias)
    const int g = lane >> 2;
    const int t = lane & 3;
#pragma unroll
    for (int mi = 0; mi < 2; mi++) {
        int row0 = bm * GBM + warp_m * 32 + mi * 16 + g;
#pragma unroll
        for (int ni = 0; ni < 4; ni++) {
            int col = bn * GBN + warp_n * 32 + ni * 8 + t * 2;
            float b0 = __ldg(bias + col);
            float b1 = __ldg(bias + col + 1);
            float2 v0 = make_float2(acc[mi][ni][0] + b0, acc[mi][ni][1] + b1);
            float2 v1 = make_float2(acc[mi][ni][2] + b0, acc[mi][ni][3] + b1);
            *(float2*)(g_h + (size_t)row0 * HDIM + col) = v0;
            *(float2*)(g_h + (size_t)(row0 + 8) * HDIM + col) = v1;
        }
    }
}

// ---------------------------------------------------------------------------
// Closed-form cross: one block per row, 128 threads.
// 4 PARALLEL dots d_l = h.w_l, one reduction, scalar recurrence, elementwise.
// ---------------------------------------------------------------------------
__global__ __launch_bounds__(128, 8) void cross_kernel(
    const float* __restrict__ ws, float* __restrict__ out)
{
    const int row  = blockIdx.x;
    const int tid  = threadIdx.x;     // 0..127
    const int wid  = tid >> 5;
    const int lane = tid & 31;

    __shared__ float red[4][4];       // [warp][layer]

    const float4* hp = (const float4*)(g_h + (size_t)row * HDIM);
    float4 x0a = hp[tid];
    float4 x0b = hp[tid + 128];

    float p[DEPTH];
#pragma unroll
    for (int l = 0; l < DEPTH; l++) {
        const float4* wp = (const float4*)(ws + l * HDIM);
        float4 wa = wp[tid];
        float4 wb = wp[tid + 128];
        p[l] = x0a.x * wa.x + x0a.y * wa.y + x0a.z * wa.z + x0a.w * wa.w
             + x0b.x * wb.x + x0b.y * wb.y + x0b.z * wb.z + x0b.w * wb.w;
    }
#pragma unroll
    for (int o = 16; o > 0; o >>= 1) {
#pragma unroll
        for (int l = 0; l < DEPTH; l++)
            p[l] += __shfl_xor_sync(0xffffffffu, p[l], o);
    }
    if (lane < DEPTH) red[wid][lane] = p[lane];
    __syncthreads();

    float a = 1.0f;
#pragma unroll
    for (int l = 0; l < DEPTH; l++) {
        float d = red[0][l] + red[1][l] + red[2][l] + red[3][l];
        a += a * d + g_e[l];
    }

    const float4* up = (const float4*)g_u4;
    float4 u0 = up[tid];
    float4 u1 = up[tid + 128];
    float4 o0, o1;
    o0.x = fmaf(a, x0a.x, u0.x); o0.y = fmaf(a, x0a.y, u0.y);
    o0.z = fmaf(a, x0a.z, u0.z); o0.w = fmaf(a, x0a.w, u0.w);
    o1.x = fmaf(a, x0b.x, u1.x); o1.y = fmaf(a, x0b.y, u1.y);
    o1.z = fmaf(a, x0b.z, u1.z); o1.w = fmaf(a, x0b.w, u1.w);

    float4* op = (float4*)(out + (size_t)row * HDIM);
    op[tid] = o0;
    op[tid + 128] = o1;
}

// ---------------------------------------------------------------------------
extern "C" void kernel_launch(void* const* d_in, const int* in_sizes, int n_in,
                              void* d_out, int out_size)
{
    const float* x     = (const float*)d_in[0];
    const float* W_enc = (const float*)d_in[1];
    const float* b_enc = (const float*)d_in[2];
    const float* ws    = (const float*)d_in[3];
    const float* bs    = (const float*)d_in[4];
    float* out = (float*)d_out;

    cudaFuncSetAttribute(gemm_mma_kernel,
                         cudaFuncAttributeMaxDynamicSharedMemorySize, GEMM_SMEM);

    convert_x_kernel<<<BDIM * KDIM / (256 * 4), 256>>>(x);
    convert_wt_kernel<<<dim3(HDIM / 32, KDIM / 32), dim3(32, 8)>>>(W_enc, ws, bs);
    gemm_mma_kernel<<<dim3(HDIM / GBN, BDIM / GBM), 256, GEMM_SMEM>>>(b_enc);
    cross_kernel<<<BDIM, 128>>>(ws, out);
}

// round 6
// speedup vs baseline: 1.2567x; 1.2567x over previous
#include <cuda_runtime.h>
#include <cuda_fp16.h>
#include <cstdint>

// ---------------------------------------------------------------------------
// CrossNetLayer on GB300 (sm_103a; PTX target compute_103 -> no tcgen05)
//   h = x @ W_enc + b_enc  -> mma.sync fp16 2-term split GEMM:
//        x = x_hi + x_lo (fp16 pair, ~exact), W rounded to fp16 (err ~2^-11)
//        h = x_hi*W + x_lo*W   (fp32 accum)
//   cross layers via closed form: out = a4(row) * h + u4
// ---------------------------------------------------------------------------

#define BDIM 1024
#define HDIM 1024
#define KDIM 1024
#define DEPTH 4

// Scratch (no cudaMalloc allowed)
__device__ float   g_h[BDIM * HDIM];
__device__ __half  g_xhi[BDIM * KDIM];
__device__ __half  g_xlo[BDIM * KDIM];
__device__ __half  g_wt[HDIM * KDIM];   // W transposed [n][k], fp16
__device__ float   g_e[DEPTH];          // e_l = u_l . w_l
__device__ float   g_u4[HDIM];          // u_4 = b0+b1+b2+b3

// ---------------------------------------------------------------------------
// helpers
// ---------------------------------------------------------------------------
__device__ __forceinline__ uint32_t smem_u32(const void* p) {
    uint32_t a;
    asm("{ .reg .u64 t; cvta.to.shared.u64 t, %1; cvt.u32.u64 %0, t; }"
        : "=r"(a) : "l"(p));
    return a;
}

__device__ __forceinline__ uint32_t swz(uint32_t off) {
    return off ^ ((off >> 3) & 0x70);   // SW128: 16B granule ^= row&7
}

__device__ __forceinline__ void cp_async16(uint32_t smem_addr, const void* gptr) {
    asm volatile("cp.async.cg.shared.global [%0], [%1], 16;"
                 :: "r"(smem_addr), "l"(gptr));
}

__device__ __forceinline__ void ldsm_x4(uint32_t* r, uint32_t addr) {
    asm volatile("ldmatrix.sync.aligned.m8n8.x4.shared.b16 {%0,%1,%2,%3}, [%4];"
                 : "=r"(r[0]), "=r"(r[1]), "=r"(r[2]), "=r"(r[3]) : "r"(addr));
}

__device__ __forceinline__ void mma_f16(float* d, const uint32_t* a, const uint32_t* b) {
    asm volatile(
        "mma.sync.aligned.m16n8k16.row.col.f32.f16.f16.f32 "
        "{%0,%1,%2,%3}, {%4,%5,%6,%7}, {%8,%9}, {%0,%1,%2,%3};"
        : "+f"(d[0]), "+f"(d[1]), "+f"(d[2]), "+f"(d[3])
        : "r"(a[0]), "r"(a[1]), "r"(a[2]), "r"(a[3]), "r"(b[0]), "r"(b[1]));
}

// ---------------------------------------------------------------------------
// Fused precompute kernel (one launch):
//   blocks [0, 1024):    x fp32 -> g_xhi/g_xlo (fp16 hi/lo split)
//   blocks [1024, 2048): W_enc transpose -> g_wt (fp16); block 1024 also
//                        computes e_l and u4.
// ---------------------------------------------------------------------------
__global__ __launch_bounds__(256, 1) void precompute_kernel(
    const float* __restrict__ x, const float* __restrict__ W,
    const float* __restrict__ ws, const float* __restrict__ bs)
{
    const int bid = blockIdx.x;
    const int tid = threadIdx.x;

    if (bid < 1024) {
        // ---- x convert ----
        int i = (bid * 256 + tid) * 4;
        float4 v = *(const float4*)(x + i);
        __half h0 = __float2half_rn(v.x);
        __half h1 = __float2half_rn(v.y);
        __half h2 = __float2half_rn(v.z);
        __half h3 = __float2half_rn(v.w);
        __half l0 = __float2half_rn(v.x - __half2float(h0));
        __half l1 = __float2half_rn(v.y - __half2float(h1));
        __half l2 = __float2half_rn(v.z - __half2float(h2));
        __half l3 = __float2half_rn(v.w - __half2float(h3));
        __half2* ph = (__half2*)(g_xhi + i);
        __half2* pl = (__half2*)(g_xlo + i);
        ph[0] = __halves2half2(h0, h1);
        ph[1] = __halves2half2(h2, h3);
        pl[0] = __halves2half2(l0, l1);
        pl[1] = __halves2half2(l2, l3);
        return;
    }

    // ---- W transpose+convert ----
    __shared__ float tile[32][33];
    const int wb = bid - 1024;
    const int bx = wb & 31;        // n tile
    const int by = wb >> 5;        // k tile
    const int tx = tid & 31;
    const int ty = tid >> 5;       // 0..7

#pragma unroll
    for (int j = 0; j < 4; j++) {
        int k = by * 32 + ty + 8 * j;
        tile[ty + 8 * j][tx] = W[(size_t)k * HDIM + bx * 32 + tx];
    }
    __syncthreads();
#pragma unroll
    for (int j = 0; j < 4; j++) {
        float v = tile[tx][ty + 8 * j];
        int n = bx * 32 + ty + 8 * j;
        int k = by * 32 + tx;
        g_wt[(size_t)n * KDIM + k] = __float2half_rn(v);
    }

    // ---- block 1024 (bx==0, by==0): e_l and u4 precompute ----
    if (wb == 0) {
        __shared__ float esum[3][8];
        const int lane = tid & 31;
        const int wrp = tid >> 5;
        float p1 = 0.f, p2 = 0.f, p3 = 0.f;
#pragma unroll
        for (int j = 0; j < 4; j++) {
            int c = tid * 4 + j;
            float b0 = bs[0 * HDIM + c];
            float b1 = bs[1 * HDIM + c];
            float b2 = bs[2 * HDIM + c];
            float b3 = bs[3 * HDIM + c];
            p1 += b0 * ws[1 * HDIM + c];
            p2 += (b0 + b1) * ws[2 * HDIM + c];
            p3 += (b0 + b1 + b2) * ws[3 * HDIM + c];
            g_u4[c] = b0 + b1 + b2 + b3;
        }
#pragma unroll
        for (int o = 16; o > 0; o >>= 1) {
            p1 += __shfl_xor_sync(0xffffffffu, p1, o);
            p2 += __shfl_xor_sync(0xffffffffu, p2, o);
            p3 += __shfl_xor_sync(0xffffffffu, p3, o);
        }
        if (lane == 0) { esum[0][wrp] = p1; esum[1][wrp] = p2; esum[2][wrp] = p3; }
        __syncthreads();
        if (tid == 0) {
            float e1 = 0.f, e2 = 0.f, e3 = 0.f;
#pragma unroll
            for (int i = 0; i < 8; i++) { e1 += esum[0][i]; e2 += esum[1][i]; e3 += esum[2][i]; }
            g_e[0] = 0.0f; g_e[1] = e1; g_e[2] = e2; g_e[3] = e3;
        }
    }
}

// ---------------------------------------------------------------------------
// mma.sync GEMM: h = x @ W_enc + bias (fp16 2-term: x_hi*W + x_lo*W)
// CTA tile: BM=128, BN=64, BK=128 (two 64-col sub-tiles). Grid (16,8) = 128.
// 8 warps in 4(M) x 2(N); warp tile 32x32. SW128 swizzle, 2-stage cp.async.
// ---------------------------------------------------------------------------
#define GBM 128
#define GBN 64
#define GKC 128
#define NCHUNK (KDIM / GKC)     // 8

// stage layout (bytes): AH[2][16384], AL[2][16384], BH[2][8192]
#define SUB_AH 0
#define SUB_AL 32768
#define SUB_BH 65536
#define STAGE_BYTES 81920
#define GEMM_SMEM (2 * STAGE_BYTES)   // 163840

__global__ __launch_bounds__(256, 1) void gemm_mma_kernel(const float* __restrict__ bias)
{
    extern __shared__ char smem[];
    const int tid  = threadIdx.x;
    const int wid  = tid >> 5;
    const int lane = tid & 31;
    const int bn   = blockIdx.x;   // 0..15
    const int bm   = blockIdx.y;   // 0..7
    const uint32_t sb = smem_u32(smem);

    const int warp_m = wid >> 1;   // 0..3
    const int warp_n = wid & 1;    // 0..1

    // ---- precomputed load addressing (advance +256B per chunk) ----
    const char* pAh[8]; const char* pAl[8]; uint32_t offA[8];
#pragma unroll
    for (int it = 0; it < 8; ++it) {
        int idx = tid + it * 256;
        int row = idx >> 4;          // 0..127
        int g   = idx & 15;          // 16B granule within 256B row
        size_t gb = ((size_t)(bm * GBM + row) * KDIM) * 2 + g * 16;
        pAh[it] = (const char*)g_xhi + gb;
        pAl[it] = (const char*)g_xlo + gb;
        offA[it] = (uint32_t)(g >> 3) * 16384 + swz(row * 128 + (g & 7) * 16);
    }
    const char* pB[4]; uint32_t offB[4];
#pragma unroll
    for (int it = 0; it < 4; ++it) {
        int idx = tid + it * 256;
        int row = idx >> 4;          // 0..63
        int g   = idx & 15;
        size_t gb = ((size_t)(bn * GBN + row) * KDIM) * 2 + g * 16;
        pB[it] = (const char*)g_wt + gb;
        offB[it] = (uint32_t)(g >> 3) * 8192 + swz(row * 128 + (g & 7) * 16);
    }

    // ---- ldmatrix per-lane offset components ----
    const int a_row_l = lane & 15;
    const int a_kb_l  = (lane >> 4) << 4;
    const int b_row_l = (lane & 7) + ((lane >> 4) << 3);
    const int b_kb_l  = ((lane >> 3) & 1) << 4;

    float acc[2][4][4];
#pragma unroll
    for (int mi = 0; mi < 2; mi++)
#pragma unroll
        for (int ni = 0; ni < 4; ni++)
#pragma unroll
            for (int j = 0; j < 4; j++) acc[mi][ni][j] = 0.0f;

    // ---- prologue: preload chunk 0 into stage 0 ----
#pragma unroll
    for (int it = 0; it < 8; ++it) {
        cp_async16(sb + SUB_AH + offA[it], pAh[it]);
        cp_async16(sb + SUB_AL + offA[it], pAl[it]);
    }
#pragma unroll
    for (int it = 0; it < 4; ++it)
        cp_async16(sb + SUB_BH + offB[it], pB[it]);
    asm volatile("cp.async.commit_group;" ::: "memory");

    for (int c = 0; c < NCHUNK; ++c) {
        asm volatile("cp.async.wait_group 0;" ::: "memory");
        __syncthreads();

        // issue loads for chunk c+1 into the other stage
        if (c + 1 < NCHUNK) {
            uint32_t dst = sb + ((c + 1) & 1) * STAGE_BYTES;
            size_t go = (size_t)(c + 1) * 256;
#pragma unroll
            for (int it = 0; it < 8; ++it) {
                cp_async16(dst + SUB_AH + offA[it], pAh[it] + go);
                cp_async16(dst + SUB_AL + offA[it], pAl[it] + go);
            }
#pragma unroll
            for (int it = 0; it < 4; ++it)
                cp_async16(dst + SUB_BH + offB[it], pB[it] + go);
            asm volatile("cp.async.commit_group;" ::: "memory");
        }

        // compute on chunk c: 2 sub-tiles x 4 k-steps
        const uint32_t base = sb + (c & 1) * STAGE_BYTES;
#pragma unroll
        for (int sub = 0; sub < 2; sub++) {
            const uint32_t baseA = base + sub * 16384;
            const uint32_t baseB = base + sub * 8192;
#pragma unroll
            for (int kk = 0; kk < 4; kk++) {
                uint32_t RAh[2][4], RAl[2][4], RB[8];
#pragma unroll
                for (int mi = 0; mi < 2; mi++) {
                    int row = warp_m * 32 + mi * 16 + a_row_l;
                    uint32_t off = swz(row * 128 + kk * 32 + a_kb_l);
                    ldsm_x4(RAh[mi], baseA + SUB_AH + off);
                    ldsm_x4(RAl[mi], baseA + SUB_AL + off);
                }
#pragma unroll
                for (int p = 0; p < 2; p++) {
                    int row = warp_n * 32 + p * 16 + b_row_l;
                    uint32_t off = swz(row * 128 + kk * 32 + b_kb_l);
                    ldsm_x4(&RB[4 * p], baseB + SUB_BH + off);
                }
#pragma unroll
                for (int mi = 0; mi < 2; mi++)
#pragma unroll
                    for (int ni = 0; ni < 4; ni++) {
                        mma_f16(acc[mi][ni], RAh[mi], &RB[2 * ni]);   // hi*W
                        mma_f16(acc[mi][ni], RAl[mi], &RB[2 * ni]);   // lo*W
                    }
            }
        }
        __syncthreads();
    }

    // epilogue: acc -> g_h (+bias)
    const int g = lane >> 2;
    const int t = lane & 3;
#pragma unroll
    for (int mi = 0; mi < 2; mi++) {
        int row0 = bm * GBM + warp_m * 32 + mi * 16 + g;
#pragma unroll
        for (int ni = 0; ni < 4; ni++) {
            int col = bn * GBN + warp_n * 32 + ni * 8 + t * 2;
            float b0 = __ldg(bias + col);
            float b1 = __ldg(bias + col + 1);
            float2 v0 = make_float2(acc[mi][ni][0] + b0, acc[mi][ni][1] + b1);
            float2 v1 = make_float2(acc[mi][ni][2] + b0, acc[mi][ni][3] + b1);
            *(float2*)(g_h + (size_t)row0 * HDIM + col) = v0;
            *(float2*)(g_h + (size_t)(row0 + 8) * HDIM + col) = v1;
        }
    }
}

// ---------------------------------------------------------------------------
// Closed-form cross: 2 rows per block (2x ILP), 128 threads, 512 blocks.
// out = a4(row)*h + u4 ; a recurrence from 4 parallel dots + precomputed e_l.
// ---------------------------------------------------------------------------
__global__ __launch_bounds__(128, 8) void cross_kernel(
    const float* __restrict__ ws, float* __restrict__ out)
{
    const int r0   = blockIdx.x * 2;
    const int r1   = r0 + 1;
    const int tid  = threadIdx.x;     // 0..127
    const int wid  = tid >> 5;
    const int lane = tid & 31;

    __shared__ float red[4][8];       // [warp][row*4+layer]

    const float4* h0p = (const float4*)(g_h + (size_t)r0 * HDIM);
    const float4* h1p = (const float4*)(g_h + (size_t)r1 * HDIM);
    float4 a0 = h0p[tid];
    float4 a1 = h0p[tid + 128];
    float4 b0 = h1p[tid];
    float4 b1 = h1p[tid + 128];
    const float4* up = (const float4*)g_u4;
    float4 u0 = up[tid];
    float4 u1 = up[tid + 128];

    float p[DEPTH], q[DEPTH];
#pragma unroll
    for (int l = 0; l < DEPTH; l++) {
        const float4* wp = (const float4*)(ws + l * HDIM);
        float4 wa = wp[tid];
        float4 wb = wp[tid + 128];
        p[l] = a0.x * wa.x + a0.y * wa.y + a0.z * wa.z + a0.w * wa.w
             + a1.x * wb.x + a1.y * wb.y + a1.z * wb.z + a1.w * wb.w;
        q[l] = b0.x * wa.x + b0.y * wa.y + b0.z * wa.z + b0.w * wa.w
             + b1.x * wb.x + b1.y * wb.y + b1.z * wb.z + b1.w * wb.w;
    }
#pragma unroll
    for (int o = 16; o > 0; o >>= 1) {
#pragma unroll
        for (int l = 0; l < DEPTH; l++) {
            p[l] += __shfl_xor_sync(0xffffffffu, p[l], o);
            q[l] += __shfl_xor_sync(0xffffffffu, q[l], o);
        }
    }
    if (lane == 0) {
#pragma unroll
        for (int l = 0; l < DEPTH; l++) {
            red[wid][l] = p[l];
            red[wid][4 + l] = q[l];
        }
    }
    __syncthreads();

    float aA = 1.0f, aB = 1.0f;
#pragma unroll
    for (int l = 0; l < DEPTH; l++) {
        float e = g_e[l];
        float dA = red[0][l] + red[1][l] + red[2][l] + red[3][l];
        float dB = red[0][4 + l] + red[1][4 + l] + red[2][4 + l] + red[3][4 + l];
        aA += aA * dA + e;
        aB += aB * dB + e;
    }

    float4 o0, o1, o2, o3;
    o0.x = fmaf(aA, a0.x, u0.x); o0.y = fmaf(aA, a0.y, u0.y);
    o0.z = fmaf(aA, a0.z, u0.z); o0.w = fmaf(aA, a0.w, u0.w);
    o1.x = fmaf(aA, a1.x, u1.x); o1.y = fmaf(aA, a1.y, u1.y);
    o1.z = fmaf(aA, a1.z, u1.z); o1.w = fmaf(aA, a1.w, u1.w);
    o2.x = fmaf(aB, b0.x, u0.x); o2.y = fmaf(aB, b0.y, u0.y);
    o2.z = fmaf(aB, b0.z, u0.z); o2.w = fmaf(aB, b0.w, u0.w);
    o3.x = fmaf(aB, b1.x, u1.x); o3.y = fmaf(aB, b1.y, u1.y);
    o3.z = fmaf(aB, b1.z, u1.z); o3.w = fmaf(aB, b1.w, u1.w);

    float4* op0 = (float4*)(out + (size_t)r0 * HDIM);
    float4* op1 = (float4*)(out + (size_t)r1 * HDIM);
    op0[tid] = o0;
    op0[tid + 128] = o1;
    op1[tid] = o2;
    op1[tid + 128] = o3;
}

// ---------------------------------------------------------------------------
extern "C" void kernel_launch(void* const* d_in, const int* in_sizes, int n_in,
                              void* d_out, int out_size)
{
    const float* x     = (const float*)d_in[0];
    const float* W_enc = (const float*)d_in[1];
    const float* b_enc = (const float*)d_in[2];
    const float* ws    = (const float*)d_in[3];
    const float* bs    = (const float*)d_in[4];
    float* out = (float*)d_out;

    cudaFuncSetAttribute(gemm_mma_kernel,
                         cudaFuncAttributeMaxDynamicSharedMemorySize, GEMM_SMEM);

    precompute_kernel<<<2048, 256>>>(x, W_enc, ws, bs);
    gemm_mma_kernel<<<dim3(HDIM / GBN, BDIM / GBM), 256, GEMM_SMEM>>>(b_enc);
    cross_kernel<<<BDIM / 2, 128>>>(ws, out);
}

// round 7
// speedup vs baseline: 1.4621x; 1.1634x over previous
#include <cuda_runtime.h>
#include <cuda_fp16.h>
#include <cstdint>

// ---------------------------------------------------------------------------
// CrossNetLayer on GB300 (sm_103a; PTX target compute_103 -> no tcgen05)
//   h = x @ W_enc + b_enc  -> mma.sync fp16 GEMM (both operands fp16-rounded,
//        fp32 accumulate; rel err ~5e-4 vs 1e-3 bound)
//   cross layers via closed form: out = a4(row) * h + u4
// ---------------------------------------------------------------------------

#define BDIM 1024
#define HDIM 1024
#define KDIM 1024
#define DEPTH 4

// Scratch (no cudaMalloc allowed)
__device__ float   g_h[BDIM * HDIM];
__device__ __half  g_x16[BDIM * KDIM];
__device__ __half  g_wt[HDIM * KDIM];   // W transposed [n][k], fp16
__device__ float   g_e[DEPTH];          // e_l = u_l . w_l
__device__ float   g_u4[HDIM];          // u_4 = b0+b1+b2+b3

// ---------------------------------------------------------------------------
// helpers
// ---------------------------------------------------------------------------
__device__ __forceinline__ uint32_t smem_u32(const void* p) {
    uint32_t a;
    asm("{ .reg .u64 t; cvta.to.shared.u64 t, %1; cvt.u32.u64 %0, t; }"
        : "=r"(a) : "l"(p));
    return a;
}

__device__ __forceinline__ uint32_t swz(uint32_t off) {
    return off ^ ((off >> 3) & 0x70);   // SW128: 16B granule ^= row&7
}

__device__ __forceinline__ void cp_async16(uint32_t smem_addr, const void* gptr) {
    asm volatile("cp.async.cg.shared.global [%0], [%1], 16;"
                 :: "r"(smem_addr), "l"(gptr));
}

__device__ __forceinline__ void ldsm_x4(uint32_t* r, uint32_t addr) {
    asm volatile("ldmatrix.sync.aligned.m8n8.x4.shared.b16 {%0,%1,%2,%3}, [%4];"
                 : "=r"(r[0]), "=r"(r[1]), "=r"(r[2]), "=r"(r[3]) : "r"(addr));
}

__device__ __forceinline__ void mma_f16(float* d, const uint32_t* a, const uint32_t* b) {
    asm volatile(
        "mma.sync.aligned.m16n8k16.row.col.f32.f16.f16.f32 "
        "{%0,%1,%2,%3}, {%4,%5,%6,%7}, {%8,%9}, {%0,%1,%2,%3};"
        : "+f"(d[0]), "+f"(d[1]), "+f"(d[2]), "+f"(d[3])
        : "r"(a[0]), "r"(a[1]), "r"(a[2]), "r"(a[3]), "r"(b[0]), "r"(b[1]));
}

// ---------------------------------------------------------------------------
// Fused precompute kernel (one launch, 1280 blocks):
//   blocks [0, 256):     x fp32 -> g_x16 (fp16), 16 floats/thread
//   blocks [256, 1280):  W_enc transpose -> g_wt (fp16); block 256 also
//                        computes e_l and u4.
// ---------------------------------------------------------------------------
__global__ __launch_bounds__(256, 1) void precompute_kernel(
    const float* __restrict__ x, const float* __restrict__ W,
    const float* __restrict__ ws, const float* __restrict__ bs)
{
    const int bid = blockIdx.x;
    const int tid = threadIdx.x;

    if (bid < 256) {
        // ---- x convert: each thread handles 16 consecutive floats ----
        int base = (bid * 256 + tid) * 16;
#pragma unroll
        for (int j = 0; j < 4; j++) {
            float4 v = *(const float4*)(x + base + 4 * j);
            __half2* ph = (__half2*)(g_x16 + base + 4 * j);
            ph[0] = __floats2half2_rn(v.x, v.y);
            ph[1] = __floats2half2_rn(v.z, v.w);
        }
        return;
    }

    // ---- W transpose+convert ----
    __shared__ float tile[32][33];
    const int wb = bid - 256;
    const int bx = wb & 31;        // n tile
    const int by = wb >> 5;        // k tile
    const int tx = tid & 31;
    const int ty = tid >> 5;       // 0..7

#pragma unroll
    for (int j = 0; j < 4; j++) {
        int k = by * 32 + ty + 8 * j;
        tile[ty + 8 * j][tx] = W[(size_t)k * HDIM + bx * 32 + tx];
    }
    __syncthreads();
#pragma unroll
    for (int j = 0; j < 4; j++) {
        float v = tile[tx][ty + 8 * j];
        int n = bx * 32 + ty + 8 * j;
        int k = by * 32 + tx;
        g_wt[(size_t)n * KDIM + k] = __float2half_rn(v);
    }

    // ---- block 256 (bx==0, by==0): e_l and u4 precompute ----
    if (wb == 0) {
        __shared__ float esum[3][8];
        const int lane = tid & 31;
        const int wrp = tid >> 5;
        float p1 = 0.f, p2 = 0.f, p3 = 0.f;
#pragma unroll
        for (int j = 0; j < 4; j++) {
            int c = tid * 4 + j;
            float b0 = bs[0 * HDIM + c];
            float b1 = bs[1 * HDIM + c];
            float b2 = bs[2 * HDIM + c];
            float b3 = bs[3 * HDIM + c];
            p1 += b0 * ws[1 * HDIM + c];
            p2 += (b0 + b1) * ws[2 * HDIM + c];
            p3 += (b0 + b1 + b2) * ws[3 * HDIM + c];
            g_u4[c] = b0 + b1 + b2 + b3;
        }
#pragma unroll
        for (int o = 16; o > 0; o >>= 1) {
            p1 += __shfl_xor_sync(0xffffffffu, p1, o);
            p2 += __shfl_xor_sync(0xffffffffu, p2, o);
            p3 += __shfl_xor_sync(0xffffffffu, p3, o);
        }
        if (lane == 0) { esum[0][wrp] = p1; esum[1][wrp] = p2; esum[2][wrp] = p3; }
        __syncthreads();
        if (tid == 0) {
            float e1 = 0.f, e2 = 0.f, e3 = 0.f;
#pragma unroll
            for (int i = 0; i < 8; i++) { e1 += esum[0][i]; e2 += esum[1][i]; e3 += esum[2][i]; }
            g_e[0] = 0.0f; g_e[1] = e1; g_e[2] = e2; g_e[3] = e3;
        }
    }
}

// ---------------------------------------------------------------------------
// mma.sync GEMM: h = x @ W_enc + bias (single-term fp16, fp32 accum)
// CTA tile: BM=128, BN=64, BK=128 (two 64-col sub-tiles). Grid (16,8) = 128.
// 8 warps in 4(M) x 2(N); warp tile 32x32. SW128 swizzle, 2-stage cp.async.
// ---------------------------------------------------------------------------
#define GBM 128
#define GBN 64
#define GKC 128
#define NCHUNK (KDIM / GKC)     // 8

// stage layout (bytes): A[2][16384], B[2][8192]
#define SUB_A 0
#define SUB_B 32768
#define STAGE_BYTES 49152
#define GEMM_SMEM (2 * STAGE_BYTES)   // 98304

__global__ __launch_bounds__(256, 1) void gemm_mma_kernel(const float* __restrict__ bias)
{
    extern __shared__ char smem[];
    const int tid  = threadIdx.x;
    const int wid  = tid >> 5;
    const int lane = tid & 31;
    const int bn   = blockIdx.x;   // 0..15
    const int bm   = blockIdx.y;   // 0..7
    const uint32_t sb = smem_u32(smem);

    const int warp_m = wid >> 1;   // 0..3
    const int warp_n = wid & 1;    // 0..1

    // ---- precomputed load addressing (advance +256B per chunk) ----
    const char* pA[8]; uint32_t offA[8];
#pragma unroll
    for (int it = 0; it < 8; ++it) {
        int idx = tid + it * 256;
        int row = idx >> 4;          // 0..127
        int g   = idx & 15;          // 16B granule within 256B row
        size_t gb = ((size_t)(bm * GBM + row) * KDIM) * 2 + g * 16;
        pA[it] = (const char*)g_x16 + gb;
        offA[it] = (uint32_t)(g >> 3) * 16384 + swz(row * 128 + (g & 7) * 16);
    }
    const char* pB[4]; uint32_t offB[4];
#pragma unroll
    for (int it = 0; it < 4; ++it) {
        int idx = tid + it * 256;
        int row = idx >> 4;          // 0..63
        int g   = idx & 15;
        size_t gb = ((size_t)(bn * GBN + row) * KDIM) * 2 + g * 16;
        pB[it] = (const char*)g_wt + gb;
        offB[it] = (uint32_t)(g >> 3) * 8192 + swz(row * 128 + (g & 7) * 16);
    }

    // ---- ldmatrix per-lane offset components ----
    const int a_row_l = lane & 15;
    const int a_kb_l  = (lane >> 4) << 4;
    const int b_row_l = (lane & 7) + ((lane >> 4) << 3);
    const int b_kb_l  = ((lane >> 3) & 1) << 4;

    float acc[2][4][4];
#pragma unroll
    for (int mi = 0; mi < 2; mi++)
#pragma unroll
        for (int ni = 0; ni < 4; ni++)
#pragma unroll
            for (int j = 0; j < 4; j++) acc[mi][ni][j] = 0.0f;

    // ---- prologue: preload chunk 0 into stage 0 ----
#pragma unroll
    for (int it = 0; it < 8; ++it)
        cp_async16(sb + SUB_A + offA[it], pA[it]);
#pragma unroll
    for (int it = 0; it < 4; ++it)
        cp_async16(sb + SUB_B + offB[it], pB[it]);
    asm volatile("cp.async.commit_group;" ::: "memory");

    for (int c = 0; c < NCHUNK; ++c) {
        asm volatile("cp.async.wait_group 0;" ::: "memory");
        __syncthreads();

        // issue loads for chunk c+1 into the other stage
        if (c + 1 < NCHUNK) {
            uint32_t dst = sb + ((c + 1) & 1) * STAGE_BYTES;
            size_t go = (size_t)(c + 1) * 256;
#pragma unroll
            for (int it = 0; it < 8; ++it)
                cp_async16(dst + SUB_A + offA[it], pA[it] + go);
#pragma unroll
            for (int it = 0; it < 4; ++it)
                cp_async16(dst + SUB_B + offB[it], pB[it] + go);
            asm volatile("cp.async.commit_group;" ::: "memory");
        }

        // compute on chunk c: 2 sub-tiles x 4 k-steps
        const uint32_t base = sb + (c & 1) * STAGE_BYTES;
#pragma unroll
        for (int sub = 0; sub < 2; sub++) {
            const uint32_t baseA = base + SUB_A + sub * 16384;
            const uint32_t baseB = base + SUB_B + sub * 8192;
#pragma unroll
            for (int kk = 0; kk < 4; kk++) {
                uint32_t RA[2][4], RB[8];
#pragma unroll
                for (int mi = 0; mi < 2; mi++) {
                    int row = warp_m * 32 + mi * 16 + a_row_l;
                    uint32_t off = swz(row * 128 + kk * 32 + a_kb_l);
                    ldsm_x4(RA[mi], baseA + off);
                }
#pragma unroll
                for (int p = 0; p < 2; p++) {
                    int row = warp_n * 32 + p * 16 + b_row_l;
                    uint32_t off = swz(row * 128 + kk * 32 + b_kb_l);
                    ldsm_x4(&RB[4 * p], baseB + off);
                }
#pragma unroll
                for (int mi = 0; mi < 2; mi++)
#pragma unroll
                    for (int ni = 0; ni < 4; ni++)
                        mma_f16(acc[mi][ni], RA[mi], &RB[2 * ni]);
            }
        }
        __syncthreads();
    }

    // epilogue: acc -> g_h (+bias)
    const int g = lane >> 2;
    const int t = lane & 3;
#pragma unroll
    for (int mi = 0; mi < 2; mi++) {
        int row0 = bm * GBM + warp_m * 32 + mi * 16 + g;
#pragma unroll
        for (int ni = 0; ni < 4; ni++) {
            int col = bn * GBN + warp_n * 32 + ni * 8 + t * 2;
            float b0 = __ldg(bias + col);
            float b1 = __ldg(bias + col + 1);
            float2 v0 = make_float2(acc[mi][ni][0] + b0, acc[mi][ni][1] + b1);
            float2 v1 = make_float2(acc[mi][ni][2] + b0, acc[mi][ni][3] + b1);
            *(float2*)(g_h + (size_t)row0 * HDIM + col) = v0;
            *(float2*)(g_h + (size_t)(row0 + 8) * HDIM + col) = v1;
        }
    }
}

// ---------------------------------------------------------------------------
// Closed-form cross: 2 rows per block (2x ILP), 128 threads, 512 blocks.
// out = a4(row)*h + u4 ; a recurrence from 4 parallel dots + precomputed e_l.
// ---------------------------------------------------------------------------
__global__ __launch_bounds__(128, 8) void cross_kernel(
    const float* __restrict__ ws, float* __restrict__ out)
{
    const int r0   = blockIdx.x * 2;
    const int r1   = r0 + 1;
    const int tid  = threadIdx.x;     // 0..127
    const int wid  = tid >> 5;
    const int lane = tid & 31;

    __shared__ float red[4][8];       // [warp][row*4+layer]

    const float4* h0p = (const float4*)(g_h + (size_t)r0 * HDIM);
    const float4* h1p = (const float4*)(g_h + (size_t)r1 * HDIM);
    float4 a0 = h0p[tid];
    float4 a1 = h0p[tid + 128];
    float4 b0 = h1p[tid];
    float4 b1 = h1p[tid + 128];
    const float4* up = (const float4*)g_u4;
    float4 u0 = up[tid];
    float4 u1 = up[tid + 128];

    float p[DEPTH], q[DEPTH];
#pragma unroll
    for (int l = 0; l < DEPTH; l++) {
        const float4* wp = (const float4*)(ws + l * HDIM);
        float4 wa = wp[tid];
        float4 wb = wp[tid + 128];
        p[l] = a0.x * wa.x + a0.y * wa.y + a0.z * wa.z + a0.w * wa.w
             + a1.x * wb.x + a1.y * wb.y + a1.z * wb.z + a1.w * wb.w;
        q[l] = b0.x * wa.x + b0.y * wa.y + b0.z * wa.z + b0.w * wa.w
             + b1.x * wb.x + b1.y * wb.y + b1.z * wb.z + b1.w * wb.w;
    }
#pragma unroll
    for (int o = 16; o > 0; o >>= 1) {
#pragma unroll
        for (int l = 0; l < DEPTH; l++) {
            p[l] += __shfl_xor_sync(0xffffffffu, p[l], o);
            q[l] += __shfl_xor_sync(0xffffffffu, q[l], o);
        }
    }
    if (lane == 0) {
#pragma unroll
        for (int l = 0; l < DEPTH; l++) {
            red[wid][l] = p[l];
            red[wid][4 + l] = q[l];
        }
    }
    __syncthreads();

    float aA = 1.0f, aB = 1.0f;
#pragma unroll
    for (int l = 0; l < DEPTH; l++) {
        float e = g_e[l];
        float dA = red[0][l] + red[1][l] + red[2][l] + red[3][l];
        float dB = red[0][4 + l] + red[1][4 + l] + red[2][4 + l] + red[3][4 + l];
        aA += aA * dA + e;
        aB += aB * dB + e;
    }

    float4 o0, o1, o2, o3;
    o0.x = fmaf(aA, a0.x, u0.x); o0.y = fmaf(aA, a0.y, u0.y);
    o0.z = fmaf(aA, a0.z, u0.z); o0.w = fmaf(aA, a0.w, u0.w);
    o1.x = fmaf(aA, a1.x, u1.x); o1.y = fmaf(aA, a1.y, u1.y);
    o1.z = fmaf(aA, a1.z, u1.z); o1.w = fmaf(aA, a1.w, u1.w);
    o2.x = fmaf(aB, b0.x, u0.x); o2.y = fmaf(aB, b0.y, u0.y);
    o2.z = fmaf(aB, b0.z, u0.z); o2.w = fmaf(aB, b0.w, u0.w);
    o3.x = fmaf(aB, b1.x, u1.x); o3.y = fmaf(aB, b1.y, u1.y);
    o3.z = fmaf(aB, b1.z, u1.z); o3.w = fmaf(aB, b1.w, u1.w);

    float4* op0 = (float4*)(out + (size_t)r0 * HDIM);
    float4* op1 = (float4*)(out + (size_t)r1 * HDIM);
    op0[tid] = o0;
    op0[tid + 128] = o1;
    op1[tid] = o2;
    op1[tid + 128] = o3;
}

// ---------------------------------------------------------------------------
extern "C" void kernel_launch(void* const* d_in, const int* in_sizes, int n_in,
                              void* d_out, int out_size)
{
    const float* x     = (const float*)d_in[0];
    const float* W_enc = (const float*)d_in[1];
    const float* b_enc = (const float*)d_in[2];
    const float* ws    = (const float*)d_in[3];
    const float* bs    = (const float*)d_in[4];
    float* out = (float*)d_out;

    cudaFuncSetAttribute(gemm_mma_kernel,
                         cudaFuncAttributeMaxDynamicSharedMemorySize, GEMM_SMEM);

    precompute_kernel<<<1280, 256>>>(x, W_enc, ws, bs);
    gemm_mma_kernel<<<dim3(HDIM / GBN, BDIM / GBM), 256, GEMM_SMEM>>>(b_enc);
    cross_kernel<<<BDIM / 2, 128>>>(ws, out);
}